// round 11
// baseline (speedup 1.0000x reference)
#include <cuda_runtime.h>

// Problem constants (match reference)
#define MASK_P   0.15f
#define MASK_LEN 8
#define B_DIM    64
#define H_DIM    512
#define W_DIM    256
#define HW       (H_DIM * W_DIM)       // 131072 pixels (each = one float4)

#define TPB      256
#define BSPLIT   2                     // batch chunks (grid.y)
#define B_PER_T  (B_DIM / BSPLIT)      // 32 batches streamed per thread

// ---------------------------------------------------------------------------
// Fused kernel (R10 structure; A/B: plain loads, evict-first stores only).
// Prologue:
//   - freq mask: 512 (batch, offset) window loads spread 2-per-thread,
//     atomicOr 4-bit channel masks into s_fbits[col].
//   - time mask: ballot over direct __ldg of time_starts.
// Body: stream 32 batches; stores use .cs (out is single-touch write-only:
// evict-first stops 128MiB of dirty write-allocate lines from thrashing L2
// across graph replays). Loads stay default to preserve cold-path behavior.
// ---------------------------------------------------------------------------
__global__ __launch_bounds__(TPB, 8)
void fused_kernel(const float4* __restrict__ x,
                  const float4* __restrict__ time_rand,   // [B,8,W] of float4
                  const float4* __restrict__ freq_rand,   // [B,H,8] of float4
                  const int*    __restrict__ time_starts,
                  const int*    __restrict__ freq_starts,
                  float4*       __restrict__ out)
{
    const int tid = threadIdx.x;
    const int pix = blockIdx.x * TPB + tid;
    const int w   = pix & (W_DIM - 1);
    const int h   = pix >> 8;                 // block-uniform (256 = one row)

    __shared__ unsigned s_tact[2];            // 64-bit time-active batch mask
    __shared__ unsigned s_fbits[W_DIM];       // per-column freq channel-zero bits

    s_fbits[tid] = 0u;
    __syncthreads();                          // zero-init before atomics

    const int warp = tid >> 5;
    const int lane = tid & 31;

    // Time-active ballot (h uniform in block).
    if (warp < 2) {
        unsigned flag =
            ((unsigned)(h - __ldg(&time_starts[tid])) < (unsigned)MASK_LEN) ? 1u : 0u;
        unsigned bal = __ballot_sync(0xFFFFFFFFu, flag);
        if (lane == 0) s_tact[warp] = bal;
    }

    // Freq windows: 512 (b, lf) pairs distributed 2-per-thread (coalesced).
    #pragma unroll
    for (int rep = 0; rep < 2; ++rep) {
        const int p  = tid + rep * TPB;
        const int b  = p >> 3;
        const int lf = p & 7;
        const int fs = __ldg(&freq_starts[b]);
        float4 fr = __ldg(&freq_rand[((size_t)b * H_DIM + h) * MASK_LEN + lf]);
        unsigned bits = (fr.x < MASK_P ? 1u : 0u)
                      | (fr.y < MASK_P ? 2u : 0u)
                      | (fr.z < MASK_P ? 4u : 0u)
                      | (fr.w < MASK_P ? 8u : 0u);
        if (bits) atomicOr(&s_fbits[fs + lf], bits);
    }
    __syncthreads();                          // fbits + tact ready

    // Combine freq bits into the 4-channel multiplier for this column.
    const unsigned fb = s_fbits[w];
    float4 m;
    m.x = (fb & 1u) ? 0.f : 1.f;
    m.y = (fb & 2u) ? 0.f : 1.f;
    m.z = (fb & 4u) ? 0.f : 1.f;
    m.w = (fb & 8u) ? 0.f : 1.f;

    // Time contributions: iterate only active bits (expected ~1 of 64).
    #pragma unroll
    for (int half = 0; half < 2; ++half) {
        unsigned act = s_tact[half];
        while (act) {
            int b = half * 32 + (__ffs(act) - 1);
            act &= act - 1;
            int lt = h - __ldg(&time_starts[b]);     // in [0, 8)
            float4 tr = __ldg(&time_rand[(b * MASK_LEN + lt) * W_DIM + w]);
            if (tr.x < MASK_P) m.x = 0.f;
            if (tr.y < MASK_P) m.y = 0.f;
            if (tr.z < MASK_P) m.z = 0.f;
            if (tr.w < MASK_P) m.w = 0.f;
        }
    }

    // ---- stream this chunk's 32 batches: plain loads, evict-first stores ----
    const int b0 = blockIdx.y * B_PER_T;
    const float4* __restrict__ xp = x   + (size_t)b0 * HW + pix;
    float4*       __restrict__ op = out + (size_t)b0 * HW + pix;

    #pragma unroll 16
    for (int b = 0; b < B_PER_T; ++b) {
        float4 v = xp[b * HW];
        v.x *= m.x; v.y *= m.y; v.z *= m.z; v.w *= m.w;
        __stcs(&op[b * HW], v);
    }
}

extern "C" void kernel_launch(void* const* d_in, const int* in_sizes, int n_in,
                              void* d_out, int out_size)
{
    const float4* x    = (const float4*)d_in[0];
    const float4* tr   = (const float4*)d_in[1];
    const float4* fr   = (const float4*)d_in[2];
    const int*    ts   = (const int*)d_in[3];
    const int*    fs   = (const int*)d_in[4];
    float4*       out  = (float4*)d_out;

    dim3 grid(HW / TPB, BSPLIT);              // 512 x 2 = 1024 blocks
    fused_kernel<<<grid, TPB>>>(x, tr, fr, ts, fs, out);
}

// round 12
// speedup vs baseline: 1.0088x; 1.0088x over previous
#include <cuda_runtime.h>

// Problem constants (match reference)
#define MASK_P   0.15f
#define MASK_LEN 8
#define B_DIM    64
#define H_DIM    512
#define W_DIM    256
#define HW       (H_DIM * W_DIM)       // 131072 pixels (each = one float4)

#define TPB      256
#define BSPLIT   2                     // batch chunks (grid.y)
#define B_PER_T  (B_DIM / BSPLIT)      // 32 batches streamed per thread

// ---------------------------------------------------------------------------
// Fused kernel (R9/R10/R11 structure; A/B cell 4: .cs loads, plain stores).
// Factorial so far: plain/plain=51.5, cs/cs=47.6, plain/cs=51.4.
// This round isolates __ldcs as the suspected active ingredient.
// ---------------------------------------------------------------------------
__global__ __launch_bounds__(TPB, 8)
void fused_kernel(const float4* __restrict__ x,
                  const float4* __restrict__ time_rand,   // [B,8,W] of float4
                  const float4* __restrict__ freq_rand,   // [B,H,8] of float4
                  const int*    __restrict__ time_starts,
                  const int*    __restrict__ freq_starts,
                  float4*       __restrict__ out)
{
    const int tid = threadIdx.x;
    const int pix = blockIdx.x * TPB + tid;
    const int w   = pix & (W_DIM - 1);
    const int h   = pix >> 8;                 // block-uniform (256 = one row)

    __shared__ unsigned s_tact[2];            // 64-bit time-active batch mask
    __shared__ unsigned s_fbits[W_DIM];       // per-column freq channel-zero bits

    s_fbits[tid] = 0u;
    __syncthreads();                          // zero-init before atomics

    const int warp = tid >> 5;
    const int lane = tid & 31;

    // Time-active ballot (h uniform in block).
    if (warp < 2) {
        unsigned flag =
            ((unsigned)(h - __ldg(&time_starts[tid])) < (unsigned)MASK_LEN) ? 1u : 0u;
        unsigned bal = __ballot_sync(0xFFFFFFFFu, flag);
        if (lane == 0) s_tact[warp] = bal;
    }

    // Freq windows: 512 (b, lf) pairs distributed 2-per-thread (coalesced).
    #pragma unroll
    for (int rep = 0; rep < 2; ++rep) {
        const int p  = tid + rep * TPB;
        const int b  = p >> 3;
        const int lf = p & 7;
        const int fs = __ldg(&freq_starts[b]);
        float4 fr = __ldg(&freq_rand[((size_t)b * H_DIM + h) * MASK_LEN + lf]);
        unsigned bits = (fr.x < MASK_P ? 1u : 0u)
                      | (fr.y < MASK_P ? 2u : 0u)
                      | (fr.z < MASK_P ? 4u : 0u)
                      | (fr.w < MASK_P ? 8u : 0u);
        if (bits) atomicOr(&s_fbits[fs + lf], bits);
    }
    __syncthreads();                          // fbits + tact ready

    // Combine freq bits into the 4-channel multiplier for this column.
    const unsigned fb = s_fbits[w];
    float4 m;
    m.x = (fb & 1u) ? 0.f : 1.f;
    m.y = (fb & 2u) ? 0.f : 1.f;
    m.z = (fb & 4u) ? 0.f : 1.f;
    m.w = (fb & 8u) ? 0.f : 1.f;

    // Time contributions: iterate only active bits (expected ~1 of 64).
    #pragma unroll
    for (int half = 0; half < 2; ++half) {
        unsigned act = s_tact[half];
        while (act) {
            int b = half * 32 + (__ffs(act) - 1);
            act &= act - 1;
            int lt = h - __ldg(&time_starts[b]);     // in [0, 8)
            float4 tr = __ldg(&time_rand[(b * MASK_LEN + lt) * W_DIM + w]);
            if (tr.x < MASK_P) m.x = 0.f;
            if (tr.y < MASK_P) m.y = 0.f;
            if (tr.z < MASK_P) m.z = 0.f;
            if (tr.w < MASK_P) m.w = 0.f;
        }
    }

    // ---- stream this chunk's 32 batches: evict-first loads, plain stores ----
    const int b0 = blockIdx.y * B_PER_T;
    const float4* __restrict__ xp = x   + (size_t)b0 * HW + pix;
    float4*       __restrict__ op = out + (size_t)b0 * HW + pix;

    #pragma unroll 16
    for (int b = 0; b < B_PER_T; ++b) {
        float4 v = __ldcs(&xp[b * HW]);
        v.x *= m.x; v.y *= m.y; v.z *= m.z; v.w *= m.w;
        op[b * HW] = v;
    }
}

extern "C" void kernel_launch(void* const* d_in, const int* in_sizes, int n_in,
                              void* d_out, int out_size)
{
    const float4* x    = (const float4*)d_in[0];
    const float4* tr   = (const float4*)d_in[1];
    const float4* fr   = (const float4*)d_in[2];
    const int*    ts   = (const int*)d_in[3];
    const int*    fs   = (const int*)d_in[4];
    float4*       out  = (float4*)d_out;

    dim3 grid(HW / TPB, BSPLIT);              // 512 x 2 = 1024 blocks
    fused_kernel<<<grid, TPB>>>(x, tr, fr, ts, fs, out);
}

// round 13
// speedup vs baseline: 1.0742x; 1.0648x over previous
#include <cuda_runtime.h>

// Problem constants (match reference)
#define MASK_P   0.15f
#define MASK_LEN 8
#define B_DIM    64
#define H_DIM    512
#define W_DIM    256
#define HW       (H_DIM * W_DIM)       // 131072 pixels (each = one float4)

#define TPB      256
#define BSPLIT   2                     // batch chunks (grid.y)
#define B_PER_T  (B_DIM / BSPLIT)      // 32 batches streamed per thread

// ---------------------------------------------------------------------------
// REPLICATION of R10 (best recorded dur_us = 47.6): .cs loads + .cs stores.
// Factorial: plain/plain=51.5, cs/cs=47.6, plain/cs=51.4, cs/plain=51.0.
// This run decides whether cs/cs is a real interaction or overhead noise.
// ---------------------------------------------------------------------------
__global__ __launch_bounds__(TPB, 8)
void fused_kernel(const float4* __restrict__ x,
                  const float4* __restrict__ time_rand,   // [B,8,W] of float4
                  const float4* __restrict__ freq_rand,   // [B,H,8] of float4
                  const int*    __restrict__ time_starts,
                  const int*    __restrict__ freq_starts,
                  float4*       __restrict__ out)
{
    const int tid = threadIdx.x;
    const int pix = blockIdx.x * TPB + tid;
    const int w   = pix & (W_DIM - 1);
    const int h   = pix >> 8;                 // block-uniform (256 = one row)

    __shared__ unsigned s_tact[2];            // 64-bit time-active batch mask
    __shared__ unsigned s_fbits[W_DIM];       // per-column freq channel-zero bits

    s_fbits[tid] = 0u;
    __syncthreads();                          // zero-init before atomics

    const int warp = tid >> 5;
    const int lane = tid & 31;

    // Time-active ballot (h uniform in block).
    if (warp < 2) {
        unsigned flag =
            ((unsigned)(h - __ldg(&time_starts[tid])) < (unsigned)MASK_LEN) ? 1u : 0u;
        unsigned bal = __ballot_sync(0xFFFFFFFFu, flag);
        if (lane == 0) s_tact[warp] = bal;
    }

    // Freq windows: 512 (b, lf) pairs distributed 2-per-thread (coalesced).
    #pragma unroll
    for (int rep = 0; rep < 2; ++rep) {
        const int p  = tid + rep * TPB;
        const int b  = p >> 3;
        const int lf = p & 7;
        const int fs = __ldg(&freq_starts[b]);
        float4 fr = __ldg(&freq_rand[((size_t)b * H_DIM + h) * MASK_LEN + lf]);
        unsigned bits = (fr.x < MASK_P ? 1u : 0u)
                      | (fr.y < MASK_P ? 2u : 0u)
                      | (fr.z < MASK_P ? 4u : 0u)
                      | (fr.w < MASK_P ? 8u : 0u);
        if (bits) atomicOr(&s_fbits[fs + lf], bits);
    }
    __syncthreads();                          // fbits + tact ready

    // Combine freq bits into the 4-channel multiplier for this column.
    const unsigned fb = s_fbits[w];
    float4 m;
    m.x = (fb & 1u) ? 0.f : 1.f;
    m.y = (fb & 2u) ? 0.f : 1.f;
    m.z = (fb & 4u) ? 0.f : 1.f;
    m.w = (fb & 8u) ? 0.f : 1.f;

    // Time contributions: iterate only active bits (expected ~1 of 64).
    #pragma unroll
    for (int half = 0; half < 2; ++half) {
        unsigned act = s_tact[half];
        while (act) {
            int b = half * 32 + (__ffs(act) - 1);
            act &= act - 1;
            int lt = h - __ldg(&time_starts[b]);     // in [0, 8)
            float4 tr = __ldg(&time_rand[(b * MASK_LEN + lt) * W_DIM + w]);
            if (tr.x < MASK_P) m.x = 0.f;
            if (tr.y < MASK_P) m.y = 0.f;
            if (tr.z < MASK_P) m.z = 0.f;
            if (tr.w < MASK_P) m.w = 0.f;
        }
    }

    // ---- stream this chunk's 32 batches (R10: evict-first both ways) ----
    const int b0 = blockIdx.y * B_PER_T;
    const float4* __restrict__ xp = x   + (size_t)b0 * HW + pix;
    float4*       __restrict__ op = out + (size_t)b0 * HW + pix;

    #pragma unroll 16
    for (int b = 0; b < B_PER_T; ++b) {
        float4 v = __ldcs(&xp[b * HW]);
        v.x *= m.x; v.y *= m.y; v.z *= m.z; v.w *= m.w;
        __stcs(&op[b * HW], v);
    }
}

extern "C" void kernel_launch(void* const* d_in, const int* in_sizes, int n_in,
                              void* d_out, int out_size)
{
    const float4* x    = (const float4*)d_in[0];
    const float4* tr   = (const float4*)d_in[1];
    const float4* fr   = (const float4*)d_in[2];
    const int*    ts   = (const int*)d_in[3];
    const int*    fs   = (const int*)d_in[4];
    float4*       out  = (float4*)d_out;

    dim3 grid(HW / TPB, BSPLIT);              // 512 x 2 = 1024 blocks
    fused_kernel<<<grid, TPB>>>(x, tr, fr, ts, fs, out);
}